// round 9
// baseline (speedup 1.0000x reference)
#include <cuda_runtime.h>
#include <cstdint>

// GaussianKDE via legacy mma.sync tf32 (single pass) + fused exp epilogue.
// out[q] = (norm/N) * a[q] * sum_n b[n] * exp2((log2e*f_q) . x_n)
// F stored pre-scaled by log2e -> epilogue is bare ex2.approx.
// K stored PERMUTED (pairs (k,k+4) adjacent) so all fragment loads are LDS.64.
// N-tiles of 256 cols, processed as two 64-col-per-warp halves under ONE
// barrier pair per tile (R7 phase structure; no in-warp interleaving).

#define DCONST 64
#define QCAP   4096
#define NCAP   50176        // 196 * 256
#define QTILE  128
#define NTILE  256
#define NCHUNK 37           // 32 q-tiles * 37 = 1184 blocks = 8 waves * 148 SMs
#define XS     72           // XS/2 == 4 (mod 16) -> LDS.64 conflict-free
#define LOG2E  1.44269504088896340736f

#define PERM(d) (((d) & 56) | (((d) & 3) << 1) | (((d) >> 2) & 1))

#define TILE_F  (128 * XS * 4)          // 36864 B
#define TILE_X  (256 * XS * 4)          // 73728 B
#define OFF_FHI 0
#define OFF_X   (OFF_FHI + TILE_F)      // 2 buffers
#define OFF_BS  (OFF_X + 2 * TILE_X)    // bs: 2 slots x 256 floats
#define OFF_RED (OFF_BS + 2048)         // red[256] floats
#define SMEM_TOTAL (OFF_RED + 1024)     // ~183 KB

__device__ float g_fhi[QCAP * DCONST];   // tf32(log2e * f), k-permuted
__device__ float g_a[QCAP];
__device__ float g_xhi[NCAP * DCONST];   // tf32(x), k-permuted
__device__ float g_b[NCAP];

// ---------------------------------------------------------------------------
__device__ __forceinline__ uint32_t smem_u32(const void* p) {
    uint32_t a;
    asm("{ .reg .u64 t; cvta.to.shared.u64 t, %1; cvt.u32.u64 %0, t; }"
        : "=r"(a) : "l"(p));
    return a;
}
__device__ __forceinline__ void cp16(uint32_t dst, const void* src) {
    asm volatile("cp.async.cg.shared.global [%0], [%1], 16;"
                 :: "r"(dst), "l"(src) : "memory");
}
__device__ __forceinline__ void mma8(float* d, const uint32_t* a,
                                     uint32_t b0, uint32_t b1) {
    asm volatile("mma.sync.aligned.m16n8k8.row.col.f32.tf32.tf32.f32 "
                 "{%0,%1,%2,%3}, {%4,%5,%6,%7}, {%8,%9}, {%0,%1,%2,%3};"
                 : "+f"(d[0]), "+f"(d[1]), "+f"(d[2]), "+f"(d[3])
                 : "r"(a[0]), "r"(a[1]), "r"(a[2]), "r"(a[3]),
                   "r"(b0), "r"(b1));
}
__device__ __forceinline__ uint32_t to_tf32_bits(float x) {
    uint32_t r;
    asm("cvt.rna.tf32.f32 %0, %1;" : "=r"(r) : "f"(x));
    return r;
}
__device__ __forceinline__ float ex2(float x) {
    float r;
    asm("ex2.approx.f32 %0, %1;" : "=f"(r) : "f"(x));
    return r;
}

// ---------------------------------------------------------------------------
// Fused prep: blocks [0, FB) do the F side, blocks [FB, ...) the X side.
__global__ void prep_kernel(const float* __restrict__ feat,
                            const float* __restrict__ bw,
                            const float* __restrict__ ds,
                            float* __restrict__ out, int Q, int N, int FB) {
    int tid = threadIdx.x;
    if ((int)blockIdx.x < FB) {
        __shared__ float bws[DCONST][DCONST];
        for (int i = tid; i < DCONST * DCONST; i += 256)
            bws[i / DCONST][i % DCONST] = bw[i];
        __syncthreads();
        int q = blockIdx.x * 256 + tid;
        if (q >= Q) return;

        float r[DCONST];
        const float4* fr = (const float4*)(feat + (size_t)q * DCONST);
#pragma unroll
        for (int v = 0; v < DCONST / 4; v++) {
            float4 t = fr[v];
            r[4 * v + 0] = t.x; r[4 * v + 1] = t.y;
            r[4 * v + 2] = t.z; r[4 * v + 3] = t.w;
        }
        float f2 = 0.0f;
#pragma unroll 4
        for (int d = 0; d < DCONST; d++) {
            float acc = 0.0f;
#pragma unroll
            for (int k = 0; k < DCONST; k++) acc = fmaf(r[k], bws[k][d], acc);
            g_fhi[(size_t)q * DCONST + PERM(d)] =
                __uint_as_float(to_tf32_bits(acc * LOG2E));
            f2 = fmaf(acc, acc, f2);
        }
        g_a[q] = expf(-0.5f * f2);
        out[q] = 0.0f;
    } else {
        int n = (blockIdx.x - FB) * 256 + tid;
        if (n >= NCAP) return;
        if (n < N) {
            float x2 = 0.0f;
            const float4* r4 = (const float4*)(ds + (size_t)n * DCONST);
#pragma unroll
            for (int v = 0; v < DCONST / 4; v++) {
                float4 t = r4[v];
                float e[4] = {t.x, t.y, t.z, t.w};
#pragma unroll
                for (int j = 0; j < 4; j++) {
                    int d = 4 * v + j;
                    g_xhi[(size_t)n * DCONST + PERM(d)] =
                        __uint_as_float(to_tf32_bits(e[j]));
                    x2 = fmaf(e[j], e[j], x2);
                }
            }
            g_b[n] = expf(-0.5f * x2);
        } else {
#pragma unroll
            for (int v = 0; v < DCONST / 4; v++)
                *(float4*)(g_xhi + (size_t)n * DCONST + 4 * v) =
                    make_float4(0, 0, 0, 0);
            g_b[n] = 0.0f;
        }
    }
}

// ---------------------------------------------------------------------------
// Main kernel: 128(Q) x 256(N) tile per block, 256 threads (8 warps).
// Warp = 32(Q) x 128(N) as two sequential 64-col halves (h=0,1).
__global__ __launch_bounds__(256, 1) void kde_mma_kernel(
    const float* __restrict__ norm, float* __restrict__ out,
    int Q, int N, int NT) {
    extern __shared__ char smem[];
    const uint32_t sb = smem_u32(smem);
    const float* fh = (const float*)(smem + OFF_FHI);
    const int tid = threadIdx.x, lane = tid & 31, wid = tid >> 5;
    const int wq = wid >> 1, wn = wid & 1;
    const int q0 = blockIdx.x * QTILE;
    const int t0 = (blockIdx.y * NT) / NCHUNK;
    const int t1 = ((blockIdx.y + 1) * NT) / NCHUNK;
    const int cnt = t1 - t0;

    // Prologue: stage F tile + first X tile + bs slot 0 (one cp.async group).
#pragma unroll
    for (int i = 0; i < 8; i++) {
        int e = tid + (i << 8);
        int row = e >> 4, c = e & 15;
        cp16(sb + OFF_FHI + row * (XS * 4) + c * 16,
             g_fhi + (size_t)(q0 + row) * DCONST + c * 4);
    }
    {
        int n0 = t0 * NTILE;
#pragma unroll
        for (int i = 0; i < 16; i++) {      // 4096 float4 for 256 rows
            int e = tid + (i << 8);
            int row = e >> 4, c = e & 15;
            cp16(sb + OFF_X + row * (XS * 4) + c * 16,
                 g_xhi + (size_t)(n0 + row) * DCONST + c * 4);
        }
        if (tid < 64) cp16(sb + OFF_BS + tid * 16, g_b + n0 + tid * 4);
    }
    asm volatile("cp.async.commit_group;");

    const int rA = wq * 32 + (lane >> 2);
    const int cA = lane & 3;
    const int colB = lane >> 2;

    uint32_t ah[2][8][4];     // A fragments (log2e-scaled), register-resident
    bool a_loaded = false;
    float racc[2][2] = {{0.f, 0.f}, {0.f, 0.f}};

    for (int j = 0; j < cnt; j++) {
        const int b = j & 1;
        if (j + 1 < cnt) {
            int n0 = (t0 + j + 1) * NTILE;
            int bb = (j + 1) & 1;
#pragma unroll
            for (int i = 0; i < 16; i++) {
                int e = tid + (i << 8);
                int row = e >> 4, c = e & 15;
                cp16(sb + OFF_X + bb * TILE_X + row * (XS * 4) + c * 16,
                     g_xhi + (size_t)(n0 + row) * DCONST + c * 4);
            }
            if (tid < 64) cp16(sb + OFF_BS + bb * 1024 + tid * 16, g_b + n0 + tid * 4);
            asm volatile("cp.async.commit_group;");
            asm volatile("cp.async.wait_group 1;");
        } else {
            asm volatile("cp.async.wait_group 0;");
        }
        __syncthreads();

        if (!a_loaded) {    // A frags via LDS.64 (permuted layout)
            a_loaded = true;
#pragma unroll
            for (int qs = 0; qs < 2; qs++)
#pragma unroll
                for (int kk = 0; kk < 8; kk++) {
                    const float* p = fh + (rA + qs * 16) * XS + kk * 8 + 2 * cA;
                    float2 t0v = *(const float2*)p;            // k=cA, k=cA+4
                    float2 t1v = *(const float2*)(p + 8 * XS);
                    ah[qs][kk][0] = __float_as_uint(t0v.x);
                    ah[qs][kk][1] = __float_as_uint(t1v.x);
                    ah[qs][kk][2] = __float_as_uint(t0v.y);
                    ah[qs][kk][3] = __float_as_uint(t1v.y);
                }
        }

        const float* xp = (const float*)(smem + OFF_X + b * TILE_X);
        const float* bsl = (const float*)(smem + OFF_BS + b * 1024);

#pragma unroll
        for (int h = 0; h < 2; h++) {
            const int nbase = wn * 128 + h * 64;   // this warp-half's N cols

            float acc[2][8][4];
#pragma unroll
            for (int qs = 0; qs < 2; qs++)
#pragma unroll
                for (int ns = 0; ns < 8; ns++)
#pragma unroll
                    for (int i = 0; i < 4; i++) acc[qs][ns][i] = 0.f;

#pragma unroll
            for (int kk = 0; kk < 8; kk++) {
#pragma unroll
                for (int ns = 0; ns < 8; ns++) {
                    const float* pb = xp + (nbase + ns * 8 + colB) * XS + kk * 8 + 2 * cA;
                    float2 bvf = *(const float2*)pb;           // LDS.64
                    uint32_t b0 = __float_as_uint(bvf.x);
                    uint32_t b1 = __float_as_uint(bvf.y);
                    mma8(acc[0][ns], ah[0][kk], b0, b1);
                    mma8(acc[1][ns], ah[1][kk], b0, b1);
                }
            }

            // Epilogue: racc += b[n] * exp2(s). Padded rows: s=0, b=0 -> no-op.
            const float* bsp = bsl + nbase + 2 * cA;
#pragma unroll
            for (int ns = 0; ns < 8; ns++) {
                float2 bv = *(const float2*)(bsp + ns * 8);
                racc[0][0] += bv.x * ex2(acc[0][ns][0]) + bv.y * ex2(acc[0][ns][1]);
                racc[0][1] += bv.x * ex2(acc[0][ns][2]) + bv.y * ex2(acc[0][ns][3]);
                racc[1][0] += bv.x * ex2(acc[1][ns][0]) + bv.y * ex2(acc[1][ns][1]);
                racc[1][1] += bv.x * ex2(acc[1][ns][2]) + bv.y * ex2(acc[1][ns][3]);
            }
        }
        __syncthreads();   // X[b]/bs reads done before buffer b is overwritten
    }

    // Reduce across the 4 lanes sharing each output row.
#pragma unroll
    for (int qs = 0; qs < 2; qs++)
#pragma unroll
        for (int h = 0; h < 2; h++) {
            float v = racc[qs][h];
            v += __shfl_xor_sync(0xffffffff, v, 1);
            v += __shfl_xor_sync(0xffffffff, v, 2);
            racc[qs][h] = v;
        }
    float* red = (float*)(smem + OFF_RED);
    if ((lane & 3) == 0) {
        int r = lane >> 2;
#pragma unroll
        for (int qs = 0; qs < 2; qs++)
#pragma unroll
            for (int h = 0; h < 2; h++)
                red[wn * 128 + wq * 32 + qs * 16 + h * 8 + r] = racc[qs][h];
    }
    __syncthreads();
    if (tid < 128) {
        int q = q0 + tid;
        if (q < Q) {
            float s = red[tid] + red[128 + tid];
            atomicAdd(&out[q], s * g_a[q] * (__ldg(norm) / (float)N));
        }
    }
}

// ---------------------------------------------------------------------------
extern "C" void kernel_launch(void* const* d_in, const int* in_sizes, int n_in,
                              void* d_out, int out_size) {
    const float* features = (const float*)d_in[0];
    const float* bw       = (const float*)d_in[1];
    const float* dataset  = (const float*)d_in[2];
    const float* norm     = (const float*)d_in[3];

    int Q = in_sizes[0] / DCONST;
    int N = in_sizes[2] / DCONST;
    int NT = (N + NTILE - 1) / NTILE;
    float* out = (float*)d_out;

    cudaFuncSetAttribute(kde_mma_kernel,
                         cudaFuncAttributeMaxDynamicSharedMemorySize, SMEM_TOTAL);

    int FB = (Q + 255) / 256;
    int XB = (NCAP + 255) / 256;
    prep_kernel<<<FB + XB, 256>>>(features, bw, dataset, out, Q, N, FB);

    dim3 grid((Q + QTILE - 1) / QTILE, NCHUNK);
    kde_mma_kernel<<<grid, 256, SMEM_TOTAL>>>(norm, out, Q, N, NT);
}

// round 11
// speedup vs baseline: 1.3128x; 1.3128x over previous
#include <cuda_runtime.h>
#include <cstdint>

// GaussianKDE via legacy mma.sync tf32 (single pass) + fused exp epilogue.
// R7 structure (best known: 222us) with: log2e folded into F (bare ex2
// epilogue), fused prep kernel, and NCHUNK=9 (2-wave grid, amortized prologue).
// out[q] = (norm/N) * a[q] * sum_n b[n] * exp2((log2e*f_q) . x_n)

#define DCONST 64
#define QCAP   4096
#define NCAP   50048        // 391 * 128
#define QTILE  128
#define NTILE  128
#define NCHUNK 9            // 32 q-tiles * 9 = 288 blocks ~= 2 waves * 148 SMs
#define XS     68           // padded smem row stride in floats (bank-conflict-free)
#define LOG2E  1.44269504088896340736f

#define OFF_FHI 0
#define TILE_B  (128 * XS * 4)          // 34816 bytes per 128x64 padded tile
#define OFF_X   (OFF_FHI + TILE_B)      // 2 buffers
#define OFF_BS  (OFF_X + 2 * TILE_B)    // bs[2][128] floats
#define OFF_RED (OFF_BS + 1024)         // red[256] floats
#define SMEM_TOTAL (OFF_RED + 1024)

__device__ float g_fhi[QCAP * DCONST];   // tf32(log2e * f)
__device__ float g_a[QCAP];
__device__ float g_xhi[NCAP * DCONST];   // tf32(x)
__device__ float g_b[NCAP];

// ---------------------------------------------------------------------------
__device__ __forceinline__ uint32_t smem_u32(const void* p) {
    uint32_t a;
    asm("{ .reg .u64 t; cvta.to.shared.u64 t, %1; cvt.u32.u64 %0, t; }"
        : "=r"(a) : "l"(p));
    return a;
}
__device__ __forceinline__ void cp16(uint32_t dst, const void* src) {
    asm volatile("cp.async.cg.shared.global [%0], [%1], 16;"
                 :: "r"(dst), "l"(src) : "memory");
}
__device__ __forceinline__ void mma8(float* d, const uint32_t* a,
                                     uint32_t b0, uint32_t b1) {
    asm volatile("mma.sync.aligned.m16n8k8.row.col.f32.tf32.tf32.f32 "
                 "{%0,%1,%2,%3}, {%4,%5,%6,%7}, {%8,%9}, {%0,%1,%2,%3};"
                 : "+f"(d[0]), "+f"(d[1]), "+f"(d[2]), "+f"(d[3])
                 : "r"(a[0]), "r"(a[1]), "r"(a[2]), "r"(a[3]),
                   "r"(b0), "r"(b1));
}
__device__ __forceinline__ uint32_t to_tf32_bits(float x) {
    uint32_t r;
    asm("cvt.rna.tf32.f32 %0, %1;" : "=r"(r) : "f"(x));
    return r;
}
__device__ __forceinline__ float ex2(float x) {
    float r;
    asm("ex2.approx.f32 %0, %1;" : "=f"(r) : "f"(x));
    return r;
}

// ---------------------------------------------------------------------------
// Fused prep: blocks [0, FB) do the F side, blocks [FB, ...) the X side.
__global__ void prep_kernel(const float* __restrict__ feat,
                            const float* __restrict__ bw,
                            const float* __restrict__ ds,
                            float* __restrict__ out, int Q, int N, int FB) {
    int tid = threadIdx.x;
    if ((int)blockIdx.x < FB) {
        // F side: f = feat @ bw; store tf32(log2e*f); a[q]; zero out[q].
        __shared__ float bws[DCONST][DCONST];
        for (int i = tid; i < DCONST * DCONST; i += 256)
            bws[i / DCONST][i % DCONST] = bw[i];
        __syncthreads();
        int q = blockIdx.x * 256 + tid;
        if (q >= Q) return;

        float r[DCONST];
        const float4* fr = (const float4*)(feat + (size_t)q * DCONST);
#pragma unroll
        for (int v = 0; v < DCONST / 4; v++) {
            float4 t = fr[v];
            r[4 * v + 0] = t.x; r[4 * v + 1] = t.y;
            r[4 * v + 2] = t.z; r[4 * v + 3] = t.w;
        }
        float f2 = 0.0f;
#pragma unroll 4
        for (int d = 0; d < DCONST; d++) {
            float acc = 0.0f;
#pragma unroll
            for (int k = 0; k < DCONST; k++) acc = fmaf(r[k], bws[k][d], acc);
            g_fhi[(size_t)q * DCONST + d] =
                __uint_as_float(to_tf32_bits(acc * LOG2E));
            f2 = fmaf(acc, acc, f2);
        }
        g_a[q] = expf(-0.5f * f2);
        out[q] = 0.0f;
    } else {
        // X side: tf32(x); b[n]; zero-pad rows [N, NCAP).
        int n = (blockIdx.x - FB) * 256 + tid;
        if (n >= NCAP) return;
        if (n < N) {
            float x2 = 0.0f;
            const float4* r4 = (const float4*)(ds + (size_t)n * DCONST);
#pragma unroll
            for (int v = 0; v < DCONST / 4; v++) {
                float4 t = r4[v];
                float e[4] = {t.x, t.y, t.z, t.w};
#pragma unroll
                for (int j = 0; j < 4; j++) {
                    g_xhi[(size_t)n * DCONST + 4 * v + j] =
                        __uint_as_float(to_tf32_bits(e[j]));
                    x2 = fmaf(e[j], e[j], x2);
                }
            }
            g_b[n] = expf(-0.5f * x2);
        } else {
#pragma unroll
            for (int v = 0; v < DCONST / 4; v++)
                *(float4*)(g_xhi + (size_t)n * DCONST + 4 * v) =
                    make_float4(0, 0, 0, 0);
            g_b[n] = 0.0f;
        }
    }
}

// ---------------------------------------------------------------------------
// Main kernel: 128(Q) x 128(N) tile per block, 256 threads (8 warps).
// Warp = 32(Q) x 64(N): wq = wid>>1 picks 32 Q-rows, wn = wid&1 picks 64 N-cols.
// A fragments for all 8 k-steps preloaded to registers once per block.
__global__ __launch_bounds__(256, 1) void kde_mma_kernel(
    const float* __restrict__ norm, float* __restrict__ out,
    int Q, int N, int NT) {
    extern __shared__ char smem[];
    const uint32_t sb = smem_u32(smem);
    const float* fh = (const float*)(smem + OFF_FHI);
    const int tid = threadIdx.x, lane = tid & 31, wid = tid >> 5;
    const int wq = wid >> 1, wn = wid & 1;
    const int q0 = blockIdx.x * QTILE;
    const int t0 = (blockIdx.y * NT) / NCHUNK;
    const int t1 = ((blockIdx.y + 1) * NT) / NCHUNK;
    const int cnt = t1 - t0;

    // Stage F tile and first X tile via cp.async (one group).
#pragma unroll
    for (int i = 0; i < 8; i++) {
        int e = tid + (i << 8);
        int row = e >> 4, c = e & 15;
        cp16(sb + OFF_FHI + row * (XS * 4) + c * 16,
             g_fhi + (size_t)(q0 + row) * DCONST + c * 4);
    }
    {
        int n0 = t0 * NTILE;
#pragma unroll
        for (int i = 0; i < 8; i++) {
            int e = tid + (i << 8);
            int row = e >> 4, c = e & 15;
            cp16(sb + OFF_X + row * (XS * 4) + c * 16,
                 g_xhi + (size_t)(n0 + row) * DCONST + c * 4);
        }
        if (tid < 32) cp16(sb + OFF_BS + tid * 16, g_b + n0 + tid * 4);
    }
    asm volatile("cp.async.commit_group;");

    const int rA = wq * 32 + (lane >> 2);
    const int cA = lane & 3;

    uint32_t ah[2][8][4];     // A fragments, all k-steps, kept in registers
    bool a_loaded = false;
    float racc[2][2] = {{0.f, 0.f}, {0.f, 0.f}};

    for (int j = 0; j < cnt; j++) {
        const int b = j & 1;
        if (j + 1 < cnt) {
            // Prefetch next X tile into the other buffer.
            int n0 = (t0 + j + 1) * NTILE;
            int bb = (j + 1) & 1;
#pragma unroll
            for (int i = 0; i < 8; i++) {
                int e = tid + (i << 8);
                int row = e >> 4, c = e & 15;
                cp16(sb + OFF_X + bb * TILE_B + row * (XS * 4) + c * 16,
                     g_xhi + (size_t)(n0 + row) * DCONST + c * 4);
            }
            if (tid < 32) cp16(sb + OFF_BS + bb * 512 + tid * 16, g_b + n0 + tid * 4);
            asm volatile("cp.async.commit_group;");
            asm volatile("cp.async.wait_group 1;");
        } else {
            asm volatile("cp.async.wait_group 0;");
        }
        __syncthreads();

        if (!a_loaded) {    // F tile resident after first wait
            a_loaded = true;
#pragma unroll
            for (int qs = 0; qs < 2; qs++)
#pragma unroll
                for (int kk = 0; kk < 8; kk++) {
                    const float* p = fh + (rA + qs * 16) * XS + kk * 8 + cA;
                    ah[qs][kk][0] = __float_as_uint(p[0]);
                    ah[qs][kk][1] = __float_as_uint(p[8 * XS]);
                    ah[qs][kk][2] = __float_as_uint(p[4]);
                    ah[qs][kk][3] = __float_as_uint(p[8 * XS + 4]);
                }
        }

        const float* xp = (const float*)(smem + OFF_X + b * TILE_B);
        float acc[2][8][4];
#pragma unroll
        for (int qs = 0; qs < 2; qs++)
#pragma unroll
            for (int ns = 0; ns < 8; ns++)
#pragma unroll
                for (int i = 0; i < 4; i++) acc[qs][ns][i] = 0.f;

#pragma unroll
        for (int kk = 0; kk < 8; kk++) {
#pragma unroll
            for (int ns = 0; ns < 8; ns++) {
                const float* pb = xp + (wn * 64 + ns * 8 + (lane >> 2)) * XS + kk * 8 + cA;
                uint32_t b0 = __float_as_uint(pb[0]);
                uint32_t b1 = __float_as_uint(pb[4]);
                mma8(acc[0][ns], ah[0][kk], b0, b1);
                mma8(acc[1][ns], ah[1][kk], b0, b1);
            }
        }

        // Fused epilogue: racc += b[n] * exp2(s). Padded rows: s=0, b=0 -> no-op.
        const float* bsp = (const float*)(smem + OFF_BS + b * 512)
                           + wn * 64 + 2 * (lane & 3);
#pragma unroll
        for (int ns = 0; ns < 8; ns++) {
            float2 bv = *(const float2*)(bsp + ns * 8);
            racc[0][0] += bv.x * ex2(acc[0][ns][0]) + bv.y * ex2(acc[0][ns][1]);
            racc[0][1] += bv.x * ex2(acc[0][ns][2]) + bv.y * ex2(acc[0][ns][3]);
            racc[1][0] += bv.x * ex2(acc[1][ns][0]) + bv.y * ex2(acc[1][ns][1]);
            racc[1][1] += bv.x * ex2(acc[1][ns][2]) + bv.y * ex2(acc[1][ns][3]);
        }
        __syncthreads();   // compute done before buffer b is overwritten
    }

    // Reduce across the 4 lanes sharing each output row.
#pragma unroll
    for (int qs = 0; qs < 2; qs++)
#pragma unroll
        for (int h = 0; h < 2; h++) {
            float v = racc[qs][h];
            v += __shfl_xor_sync(0xffffffff, v, 1);
            v += __shfl_xor_sync(0xffffffff, v, 2);
            racc[qs][h] = v;
        }
    float* red = (float*)(smem + OFF_RED);
    if ((lane & 3) == 0) {
        int r = lane >> 2;
#pragma unroll
        for (int qs = 0; qs < 2; qs++)
#pragma unroll
            for (int h = 0; h < 2; h++)
                red[wn * 128 + wq * 32 + qs * 16 + h * 8 + r] = racc[qs][h];
    }
    __syncthreads();
    if (tid < 128) {
        int q = q0 + tid;
        if (q < Q) {
            float s = red[tid] + red[128 + tid];
            atomicAdd(&out[q], s * g_a[q] * (__ldg(norm) / (float)N));
        }
    }
}

// ---------------------------------------------------------------------------
extern "C" void kernel_launch(void* const* d_in, const int* in_sizes, int n_in,
                              void* d_out, int out_size) {
    const float* features = (const float*)d_in[0];
    const float* bw       = (const float*)d_in[1];
    const float* dataset  = (const float*)d_in[2];
    const float* norm     = (const float*)d_in[3];

    int Q = in_sizes[0] / DCONST;
    int N = in_sizes[2] / DCONST;
    int NT = (N + NTILE - 1) / NTILE;
    float* out = (float*)d_out;

    cudaFuncSetAttribute(kde_mma_kernel,
                         cudaFuncAttributeMaxDynamicSharedMemorySize, SMEM_TOTAL);

    int FB = (Q + 255) / 256;
    int XB = (NCAP + 255) / 256;
    prep_kernel<<<FB + XB, 256>>>(features, bw, dataset, out, Q, N, FB);

    dim3 grid((Q + QTILE - 1) / QTILE, NCHUNK);
    kde_mma_kernel<<<grid, 256, SMEM_TOTAL>>>(norm, out, Q, N, NT);
}